// round 1
// baseline (speedup 1.0000x reference)
#include <cuda_runtime.h>
#include <cstdint>

#define QNL 6

// Coefficient block computed by the prelude kernel:
// [0]           K (constant term incl. b2[1]-b2[0])
// [1..8]        circuit-1 coeffs for {cb, sb, ca, ca*cb, ca*sb, sa, sa*cb, sa*sb}
// [9..16]       circuit-2 coeffs, same order
// [17..28]      angle affine maps: 4 rows of (w_x0, w_x1, bias) for a1,b1,a2,b2
__device__ float g_C[32];

struct cpx { float x, y; };
__device__ __forceinline__ cpx cmul(cpx a, cpx b){ return cpx{a.x*b.x - a.y*b.y, a.x*b.y + a.y*b.x}; }
__device__ __forceinline__ cpx cadd(cpx a, cpx b){ return cpx{a.x + b.x, a.y + b.y}; }

// 32 threads: lanes 0-15 -> circuit 1 (qw1, W2 cols 0,1), lanes 16-31 -> circuit 2.
// Each lane owns one (row I, col J) entry of the 4x4 matrices.
__global__ void prelude_kernel(const float* __restrict__ qw1, const float* __restrict__ qw2,
                               const float* __restrict__ W1, const float* __restrict__ b1,
                               const float* __restrict__ W2, const float* __restrict__ b2)
{
    __shared__ cpx U[2][4][4];
    __shared__ cpx M[2][2][4][4];
    __shared__ float Kpart[2];

    int t = threadIdx.x;
    int c = t >> 4;          // circuit
    int e = t & 15;          // matrix entry
    int I = e >> 2, J = e & 3;
    const float* qw = c ? qw2 : qw1;

    U[c][I][J] = cpx{ (I == J) ? 1.0f : 0.0f, 0.0f };
    __syncwarp();

    // CNOT(control q0, target q1) permutes rows 2<->3; fold into which T-row we compute.
    int S  = (I < 2) ? I : (5 - I);
    int iS = S >> 1, jS = S & 1;

    for (int l = 0; l < QNL; l++){
        float s0, c0, s1, c1;
        __sincosf(qw[2*l + 0] * 0.5f, &s0, &c0);
        __sincosf(qw[2*l + 1] * 0.5f, &s1, &c1);
        // RX(th) = [[c, -i s], [-i s, c]];  G = R0 (x) R1;  T = G * U (row S), then CNOT perm.
        cpx T = cpx{0.f, 0.f};
        #pragma unroll
        for (int K = 0; K < 4; K++){
            int kS = K >> 1, lS = K & 1;
            cpx r0 = (iS == kS) ? cpx{c0, 0.f} : cpx{0.f, -s0};
            cpx r1 = (jS == lS) ? cpx{c1, 0.f} : cpx{0.f, -s1};
            T = cadd(T, cmul(cmul(r0, r1), U[c][K][J]));
        }
        __syncwarp();
        U[c][I][J] = T;
        __syncwarp();
    }

    // M_m = U^dag D_m U with D0 = Z(x)I = diag(1,1,-1,-1), D1 = I(x)Z = diag(1,-1,1,-1)
    cpx m0 = cpx{0.f,0.f}, m1 = cpx{0.f,0.f};
    #pragma unroll
    for (int K = 0; K < 4; K++){
        cpx a = U[c][K][I];
        cpx b = U[c][K][J];
        cpx tK = cmul(cpx{a.x, -a.y}, b);
        float d0 = (K < 2)  ?  1.f : -1.f;
        float d1 = (K & 1)  ? -1.f :  1.f;
        m0.x += d0*tK.x; m0.y += d0*tK.y;
        m1.x += d1*tK.x; m1.y += d1*tK.y;
    }
    M[c][0][I][J] = m0;
    M[c][1][I][J] = m1;
    __syncwarp();

    // z_m(a,b) = (1/4) sum_{alpha,beta in {I,Z,Y}} f_alpha(a) f_beta(b) * sum_{IJ} (Pa(x)Pb)_IJ * M_IJ
    // lane e = alpha*3+beta handles one basis pair for both m, combined with (W2 row1 - row0).
    if (e < 9){
        int alpha = e / 3, beta = e % 3;  // 0=I, 1=Z(cos), 2=Y(sin)
        float C0 = 0.f, C1 = 0.f;
        #pragma unroll
        for (int ra = 0; ra < 2; ra++){
            int ia = ra;
            int ka = (alpha == 2) ? 1 - ra : ra;
            cpx va = (alpha == 0) ? cpx{1.f, 0.f}
                   : (alpha == 1) ? cpx{ra ? -1.f : 1.f, 0.f}
                                  : cpx{0.f, ra ? 1.f : -1.f};   // Y: (0,1)->-i, (1,0)->+i
            #pragma unroll
            for (int rb = 0; rb < 2; rb++){
                int ib = rb;
                int kb = (beta == 2) ? 1 - rb : rb;
                cpx vb = (beta == 0) ? cpx{1.f, 0.f}
                       : (beta == 1) ? cpx{rb ? -1.f : 1.f, 0.f}
                                     : cpx{0.f, rb ? 1.f : -1.f};
                cpx v = cmul(va, vb);
                cpx e0 = M[c][0][2*ia + ib][2*ka + kb];
                cpx e1 = M[c][1][2*ia + ib][2*ka + kb];
                C0 += v.x*e0.x - v.y*e0.y;   // Re(v * M)
                C1 += v.x*e1.x - v.y*e1.y;
            }
        }
        float w0 = W2[4 + 2*c + 0] - W2[2*c + 0];
        float w1 = W2[4 + 2*c + 1] - W2[2*c + 1];
        float g = 0.25f * (w0*C0 + w1*C1);
        if (e == 0) Kpart[c] = g;
        else        g_C[8*c + e] = g;        // c=0 -> [1..8], c=1 -> [9..16]
    }
    __syncwarp();
    if (t == 0) g_C[0] = (b2[1] - b2[0]) + Kpart[0] + Kpart[1];
    // angle maps: row r uses W1[r][0], W1[r][1], b1[r]
    if (t < 12) g_C[17 + t] = ((t % 3) == 2) ? b1[t / 3] : W1[(t / 3) * 2 + (t % 3)];
}

__device__ __forceinline__ float2 eval_one(float x0, float x1, const float* C){
    float a1 = fmaf(C[17], x0, fmaf(C[18], x1, C[19]));
    float b1 = fmaf(C[20], x0, fmaf(C[21], x1, C[22]));
    float a2 = fmaf(C[23], x0, fmaf(C[24], x1, C[25]));
    float b2 = fmaf(C[26], x0, fmaf(C[27], x1, C[28]));
    float sa, ca, sb, cb;
    float d = C[0];
    __sincosf(a1, &sa, &ca);
    __sincosf(b1, &sb, &cb);
    d = fmaf(C[1], cb, d);
    d = fmaf(C[2], sb, d);
    d = fmaf(C[3], ca, d);
    d = fmaf(C[4], ca*cb, d);
    d = fmaf(C[5], ca*sb, d);
    d = fmaf(C[6], sa, d);
    d = fmaf(C[7], sa*cb, d);
    d = fmaf(C[8], sa*sb, d);
    __sincosf(a2, &sa, &ca);
    __sincosf(b2, &sb, &cb);
    d = fmaf(C[9],  cb, d);
    d = fmaf(C[10], sb, d);
    d = fmaf(C[11], ca, d);
    d = fmaf(C[12], ca*cb, d);
    d = fmaf(C[13], ca*sb, d);
    d = fmaf(C[14], sa, d);
    d = fmaf(C[15], sa*cb, d);
    d = fmaf(C[16], sa*sb, d);
    // stable 2-way softmax: out = (sigmoid(-d), sigmoid(d)), d = logit1 - logit0
    float ed = __expf(-fabsf(d));
    float s  = __fdividef(ed, 1.0f + ed);
    float o0 = (d > 0.f) ? s : (1.0f - s);
    return make_float2(o0, 1.0f - o0);
}

__global__ __launch_bounds__(256) void hybrid_main(const float4* __restrict__ xin,
                                                   float4* __restrict__ out, int nf4){
    float C[29];
    #pragma unroll
    for (int i = 0; i < 29; i++) C[i] = g_C[i];
    int t = blockIdx.x * blockDim.x + threadIdx.x;
    int stride = gridDim.x * blockDim.x;
    for (int i = t; i < nf4; i += stride){
        float4 v = __ldg(&xin[i]);                 // 2 batch elements per float4
        float2 r0 = eval_one(v.x, v.y, C);
        float2 r1 = eval_one(v.z, v.w, C);
        out[i] = make_float4(r0.x, r0.y, r1.x, r1.y);
    }
}

extern "C" void kernel_launch(void* const* d_in, const int* in_sizes, int n_in,
                              void* d_out, int out_size){
    const float* x   = (const float*)d_in[0];
    const float* W1  = (const float*)d_in[1];
    const float* b1  = (const float*)d_in[2];
    const float* qw1 = (const float*)d_in[3];
    const float* qw2 = (const float*)d_in[4];
    const float* W2  = (const float*)d_in[5];
    const float* b2  = (const float*)d_in[6];

    prelude_kernel<<<1, 32>>>(qw1, qw2, W1, b1, W2, b2);

    int nf4 = in_sizes[0] / 4;        // (B*2 floats) / 4 = one float4 per 2 elements
    int grid = 2048;                  // 524288 threads, 2 float4 per thread via grid-stride
    hybrid_main<<<grid, 256>>>((const float4*)x, (float4*)d_out, nf4);
}